// round 3
// baseline (speedup 1.0000x reference)
#include <cuda_runtime.h>
#include <math.h>

// ---------------------------------------------------------------------------
// GaussianSplattingCompliance: N_POINTS=131072, N_G=256
//   kernel = sigmoid(-10(z-1)) = 0.5 - 0.5*tanh(5(z-1))
// Per gaussian precompute affine with factor 5 absorbed:
//   u = A1*cx+B1*cy+C1, v = A2*cx+B2*cy+C2,  sqrt(u^2+v^2) == 5z
//   t = tanh.approx(sqrt(uu+vv) - 5),  ks = 128 - 0.5*sum(t) + 1e-8
// Main kernel: 2 points/thread, all FMA math in packed f32x2.
// ---------------------------------------------------------------------------

#define N_POINTS 131072
#define N_G      256
#define PRE_BLOCKS 256

__device__ unsigned g_enc[4];      // enc(max x), enc(max y), enc(max -x), enc(max -y)
__device__ unsigned g_count;
__device__ float4   g_AB[N_G];     // A1,B1,A2,B2
__device__ float2   g_C[N_G];      // C1,C2

__device__ __forceinline__ unsigned f_enc(float f) {
    unsigned u = __float_as_uint(f);
    return (u & 0x80000000u) ? ~u : (u | 0x80000000u);
}
__device__ __forceinline__ float f_dec(unsigned e) {
    unsigned u = (e & 0x80000000u) ? (e ^ 0x80000000u) : ~e;
    return __uint_as_float(u);
}
__device__ __forceinline__ float sigmoid_f(float x) {
    return 1.0f / (1.0f + expf(-x));
}

// ---------------- fused prologue: minmax + params + scratch reset -----------
__global__ void __launch_bounds__(256)
gs_pre_kernel(const float4* __restrict__ coords4,
              const float*  __restrict__ W_scale,
              const float*  __restrict__ W_shape_var,
              const float*  __restrict__ W_rotation,
              const float2* __restrict__ W_offsets) {
    __shared__ float s_red[8][4];
    __shared__ int   s_last;
    int tid = threadIdx.x;

    float4 q = coords4[blockIdx.x * 256 + tid];
    float mxx = fmaxf(q.x, q.z), mxy = fmaxf(q.y, q.w);
    float nmx = -fminf(q.x, q.z), nmy = -fminf(q.y, q.w);

    #pragma unroll
    for (int o = 16; o > 0; o >>= 1) {
        mxx = fmaxf(mxx, __shfl_xor_sync(0xffffffffu, mxx, o));
        mxy = fmaxf(mxy, __shfl_xor_sync(0xffffffffu, mxy, o));
        nmx = fmaxf(nmx, __shfl_xor_sync(0xffffffffu, nmx, o));
        nmy = fmaxf(nmy, __shfl_xor_sync(0xffffffffu, nmy, o));
    }
    int wid = tid >> 5, lid = tid & 31;
    if (lid == 0) {
        s_red[wid][0] = mxx; s_red[wid][1] = mxy;
        s_red[wid][2] = nmx; s_red[wid][3] = nmy;
    }
    __syncthreads();
    if (tid == 0) {
        float a = s_red[0][0], b = s_red[0][1], c = s_red[0][2], d = s_red[0][3];
        #pragma unroll
        for (int w = 1; w < 8; w++) {
            a = fmaxf(a, s_red[w][0]); b = fmaxf(b, s_red[w][1]);
            c = fmaxf(c, s_red[w][2]); d = fmaxf(d, s_red[w][3]);
        }
        atomicMax(&g_enc[0], f_enc(a));
        atomicMax(&g_enc[1], f_enc(b));
        atomicMax(&g_enc[2], f_enc(c));
        atomicMax(&g_enc[3], f_enc(d));
        __threadfence();
        unsigned done = atomicAdd(&g_count, 1u);
        s_last = (done == PRE_BLOCKS - 1) ? 1 : 0;
    }
    __syncthreads();
    if (!s_last) return;

    float cmaxx = f_dec(atomicMax(&g_enc[0], 0u));
    float cmaxy = f_dec(atomicMax(&g_enc[1], 0u));
    float cminx = -f_dec(atomicMax(&g_enc[2], 0u));
    float cminy = -f_dec(atomicMax(&g_enc[3], 0u));

    float lo_x = cminx - cmaxx * 0.05f, hi_x = cmaxx + cmaxx * 0.05f;
    float lo_y = cminy - cmaxy * 0.05f, hi_y = cmaxy + cmaxy * 0.05f;

    int b = tid;
    float base_scale = (1.5f - 0.05f) * sigmoid_f(W_scale[b]) + 0.05f;
    float ratio      = (3.5f - 0.5f) * sigmoid_f(W_shape_var[b]) + 0.5f;
    const float PI_F = 3.14159265358979323846f;
    float rot        = -0.5f * PI_F + PI_F * sigmoid_f(W_rotation[b]);
    float2 wo = W_offsets[b];
    float ox = lo_x + (hi_x - lo_x) * sigmoid_f(wo.x);
    float oy = lo_y + (hi_y - lo_y) * sigmoid_f(wo.y);

    float inv_s = 1.0f / (base_scale + 1e-8f);
    float sq0 = sqrtf(1.0f / (1.0f + 1e-6f));
    float sq1 = sqrtf(1.0f / (ratio * ratio + 1e-6f));
    float c = cosf(rot), s = sinf(rot);

    float k0 = 5.0f * inv_s * sq0;
    float k1 = 5.0f * inv_s * sq1;
    float A1 =  c * k0, B1 = -s * k0;
    float A2 =  s * k1, B2 =  c * k1;
    float C1 = -(A1 * ox + B1 * oy);
    float C2 = -(A2 * ox + B2 * oy);

    g_AB[b] = make_float4(A1, B1, A2, B2);
    g_C[b]  = make_float2(C1, C2);

    if (tid < 4) g_enc[tid] = 0u;
    if (tid == 0) g_count = 0u;
}

// ---------------- main kernel: 2 points/thread, packed f32x2 math ----------

#define FMA2(d, a, b, c) \
    asm("fma.rn.f32x2 %0, %1, %2, %3;" : "=l"(d) : "l"(a), "l"(b), "l"(c))
#define MUL2(d, a, b) \
    asm("mul.rn.f32x2 %0, %1, %2;" : "=l"(d) : "l"(a), "l"(b))
#define PACK2(d, lo, hi) \
    asm("mov.b64 %0, {%1, %2};" : "=l"(d) : "f"(lo), "f"(hi))
#define UNPACK2(lo, hi, s) \
    asm("mov.b64 {%0, %1}, %2;" : "=f"(lo), "=f"(hi) : "l"(s))

__global__ void __launch_bounds__(64)
gs_main_kernel(const float4* __restrict__ coords4, float2* __restrict__ out) {
    // per gaussian: 3 b64-pairs, each duplicated scalar:
    //   sP[3g+0] = {A1A1, B1B1}, sP[3g+1] = {A2A2, B2B2}, sP[3g+2] = {C1C1, C2C2}
    __shared__ ulonglong2 sP[N_G * 3];
    int t = threadIdx.x;

    for (int g = t; g < N_G; g += 64) {
        float4 ab = g_AB[g];
        float2 cc = g_C[g];
        float4* dst = (float4*)&sP[3 * g];
        dst[0] = make_float4(ab.x, ab.x, ab.y, ab.y);
        dst[1] = make_float4(ab.z, ab.z, ab.w, ab.w);
        dst[2] = make_float4(cc.x, cc.x, cc.y, cc.y);
    }
    __syncthreads();

    int i = blockIdx.x * 64 + t;          // float4 index: points 2i, 2i+1
    float4 p = coords4[i];
    unsigned long long cxx, cyy;
    PACK2(cxx, p.x, p.z);                 // {x0, x1}
    PACK2(cyy, p.y, p.w);                 // {y0, y1}

    float sum0 = 0.0f, sum1 = 0.0f;
    #pragma unroll 8
    for (int g = 0; g < N_G; g++) {
        ulonglong2 q0 = sP[3 * g + 0];    // {A1A1, B1B1}
        ulonglong2 q1 = sP[3 * g + 1];    // {A2A2, B2B2}
        ulonglong2 q2 = sP[3 * g + 2];    // {C1C1, C2C2}
        unsigned long long u, v, ss, t1;
        FMA2(t1, q0.y, cyy, q2.x);        // B1*cy + C1
        FMA2(u,  q0.x, cxx, t1);          // A1*cx + ...
        FMA2(t1, q1.y, cyy, q2.y);        // B2*cy + C2
        FMA2(v,  q1.x, cxx, t1);          // A2*cx + ...
        MUL2(t1, v, v);
        FMA2(ss, u, u, t1);               // u^2 + v^2 (both points)

        float s0, s1;
        UNPACK2(s0, s1, ss);
        float zp0, zp1, th0, th1;
        asm("sqrt.approx.f32 %0, %1;" : "=f"(zp0) : "f"(s0));
        asm("sqrt.approx.f32 %0, %1;" : "=f"(zp1) : "f"(s1));
        asm("tanh.approx.f32 %0, %1;" : "=f"(th0) : "f"(zp0 - 5.0f));
        asm("tanh.approx.f32 %0, %1;" : "=f"(th1) : "f"(zp1 - 5.0f));
        sum0 += th0;
        sum1 += th1;
    }

    // ks = 128 - 0.5*sum + 1e-8 ; H = (1-1e-9)*sigmoid(-10(ks-0.5)) + 1e-9
    float ks0 = fmaf(-0.5f, sum0, 128.0f) + 1e-8f;
    float ks1 = fmaf(-0.5f, sum1, 128.0f) + 1e-8f;
    float e0 = __expf(10.0f * (ks0 - 0.5f));
    float e1 = __expf(10.0f * (ks1 - 0.5f));
    float2 H;
    H.x = (1.0f - 1e-9f) / (1.0f + e0) + 1e-9f;
    H.y = (1.0f - 1e-9f) / (1.0f + e1) + 1e-9f;
    out[i] = H;
}

extern "C" void kernel_launch(void* const* d_in, const int* in_sizes, int n_in,
                              void* d_out, int out_size) {
    const float4* coords4     = (const float4*)d_in[0];   // 65536 float4 = 131072 pts
    const float*  W_scale     = (const float*)d_in[1];
    const float*  W_shape_var = (const float*)d_in[2];
    const float*  W_rotation  = (const float*)d_in[3];
    const float2* W_offsets   = (const float2*)d_in[4];
    float2* out = (float2*)d_out;

    gs_pre_kernel<<<PRE_BLOCKS, 256>>>(coords4, W_scale, W_shape_var,
                                       W_rotation, W_offsets);
    gs_main_kernel<<<(N_POINTS / 2) / 64, 64>>>(coords4, out);
}

// round 4
// speedup vs baseline: 1.2220x; 1.2220x over previous
#include <cuda_runtime.h>
#include <math.h>

// ---------------------------------------------------------------------------
// GaussianSplattingCompliance: N_POINTS=131072, N_G=256
//   kernel = sigmoid(-10(z-1)) = 0.5 - 0.5*tanh(5(z-1))
// Per gaussian precompute affine with factor 5 absorbed:
//   u = A1*cx+B1*cy+C1, v = A2*cx+B2*cy+C2,  sqrt(u^2+v^2) == 5z
//   t = tanh.approx(sqrt(uu+vv) - 5),  ks = 128 - 0.5*sum(t) + 1e-8
// Main kernel: 1 point/thread, 2 gaussians per packed f32x2 op.
// ---------------------------------------------------------------------------

#define N_POINTS 131072
#define N_G      256
#define PRE_BLOCKS 256

__device__ unsigned g_enc[4];      // enc(max x), enc(max y), enc(max -x), enc(max -y)
__device__ unsigned g_count;
__device__ float4   g_AB[N_G];     // A1,B1,A2,B2
__device__ float2   g_C[N_G];      // C1,C2

__device__ __forceinline__ unsigned f_enc(float f) {
    unsigned u = __float_as_uint(f);
    return (u & 0x80000000u) ? ~u : (u | 0x80000000u);
}
__device__ __forceinline__ float f_dec(unsigned e) {
    unsigned u = (e & 0x80000000u) ? (e ^ 0x80000000u) : ~e;
    return __uint_as_float(u);
}
__device__ __forceinline__ float sigmoid_f(float x) {
    return 1.0f / (1.0f + expf(-x));
}

// ---------------- fused prologue: minmax + params + scratch reset -----------
__global__ void __launch_bounds__(256)
gs_pre_kernel(const float4* __restrict__ coords4,
              const float*  __restrict__ W_scale,
              const float*  __restrict__ W_shape_var,
              const float*  __restrict__ W_rotation,
              const float2* __restrict__ W_offsets) {
    __shared__ float s_red[8][4];
    __shared__ int   s_last;
    int tid = threadIdx.x;

    float4 q = coords4[blockIdx.x * 256 + tid];
    float mxx = fmaxf(q.x, q.z), mxy = fmaxf(q.y, q.w);
    float nmx = -fminf(q.x, q.z), nmy = -fminf(q.y, q.w);

    #pragma unroll
    for (int o = 16; o > 0; o >>= 1) {
        mxx = fmaxf(mxx, __shfl_xor_sync(0xffffffffu, mxx, o));
        mxy = fmaxf(mxy, __shfl_xor_sync(0xffffffffu, mxy, o));
        nmx = fmaxf(nmx, __shfl_xor_sync(0xffffffffu, nmx, o));
        nmy = fmaxf(nmy, __shfl_xor_sync(0xffffffffu, nmy, o));
    }
    int wid = tid >> 5, lid = tid & 31;
    if (lid == 0) {
        s_red[wid][0] = mxx; s_red[wid][1] = mxy;
        s_red[wid][2] = nmx; s_red[wid][3] = nmy;
    }
    __syncthreads();
    if (tid == 0) {
        float a = s_red[0][0], b = s_red[0][1], c = s_red[0][2], d = s_red[0][3];
        #pragma unroll
        for (int w = 1; w < 8; w++) {
            a = fmaxf(a, s_red[w][0]); b = fmaxf(b, s_red[w][1]);
            c = fmaxf(c, s_red[w][2]); d = fmaxf(d, s_red[w][3]);
        }
        atomicMax(&g_enc[0], f_enc(a));
        atomicMax(&g_enc[1], f_enc(b));
        atomicMax(&g_enc[2], f_enc(c));
        atomicMax(&g_enc[3], f_enc(d));
        __threadfence();
        unsigned done = atomicAdd(&g_count, 1u);
        s_last = (done == PRE_BLOCKS - 1) ? 1 : 0;
    }
    __syncthreads();
    if (!s_last) return;

    float cmaxx = f_dec(atomicMax(&g_enc[0], 0u));
    float cmaxy = f_dec(atomicMax(&g_enc[1], 0u));
    float cminx = -f_dec(atomicMax(&g_enc[2], 0u));
    float cminy = -f_dec(atomicMax(&g_enc[3], 0u));

    float lo_x = cminx - cmaxx * 0.05f, hi_x = cmaxx + cmaxx * 0.05f;
    float lo_y = cminy - cmaxy * 0.05f, hi_y = cmaxy + cmaxy * 0.05f;

    int b = tid;
    float base_scale = (1.5f - 0.05f) * sigmoid_f(W_scale[b]) + 0.05f;
    float ratio      = (3.5f - 0.5f) * sigmoid_f(W_shape_var[b]) + 0.5f;
    const float PI_F = 3.14159265358979323846f;
    float rot        = -0.5f * PI_F + PI_F * sigmoid_f(W_rotation[b]);
    float2 wo = W_offsets[b];
    float ox = lo_x + (hi_x - lo_x) * sigmoid_f(wo.x);
    float oy = lo_y + (hi_y - lo_y) * sigmoid_f(wo.y);

    float inv_s = 1.0f / (base_scale + 1e-8f);
    float sq0 = sqrtf(1.0f / (1.0f + 1e-6f));
    float sq1 = sqrtf(1.0f / (ratio * ratio + 1e-6f));
    float c = cosf(rot), s = sinf(rot);

    float k0 = 5.0f * inv_s * sq0;
    float k1 = 5.0f * inv_s * sq1;
    float A1 =  c * k0, B1 = -s * k0;
    float A2 =  s * k1, B2 =  c * k1;
    float C1 = -(A1 * ox + B1 * oy);
    float C2 = -(A2 * ox + B2 * oy);

    g_AB[b] = make_float4(A1, B1, A2, B2);
    g_C[b]  = make_float2(C1, C2);

    if (tid < 4) g_enc[tid] = 0u;
    if (tid == 0) g_count = 0u;
}

// ---------------- main kernel: 1 point/thread, 2 gaussians per f32x2 --------

#define FMA2(d, a, b, c) \
    asm("fma.rn.f32x2 %0, %1, %2, %3;" : "=l"(d) : "l"(a), "l"(b), "l"(c))
#define MUL2(d, a, b) \
    asm("mul.rn.f32x2 %0, %1, %2;" : "=l"(d) : "l"(a), "l"(b))
#define PACK2(d, lo, hi) \
    asm("mov.b64 %0, {%1, %2};" : "=l"(d) : "f"(lo), "f"(hi))
#define UNPACK2(lo, hi, s) \
    asm("mov.b64 {%0, %1}, %2;" : "=f"(lo), "=f"(hi) : "l"(s))

#define N_PAIR (N_G / 2)   // 128 gaussian pairs

__global__ void __launch_bounds__(128)
gs_main_kernel(const float2* __restrict__ coords, float* __restrict__ out) {
    // per gaussian PAIR p (gaussians 2p, 2p+1), 3 x 16B entries:
    //   sP[3p+0] = {A1_e, A1_o, B1_e, B1_o}
    //   sP[3p+1] = {A2_e, A2_o, B2_e, B2_o}
    //   sP[3p+2] = {C1_e, C1_o, C2_e, C2_o}
    __shared__ ulonglong2 sP[N_PAIR * 3];
    int t = threadIdx.x;

    if (t < N_PAIR) {
        float4 abE = g_AB[2 * t];
        float4 abO = g_AB[2 * t + 1];
        float2 cE  = g_C[2 * t];
        float2 cO  = g_C[2 * t + 1];
        float4* dst = (float4*)&sP[3 * t];
        dst[0] = make_float4(abE.x, abO.x, abE.y, abO.y);   // A1A1,B1B1
        dst[1] = make_float4(abE.z, abO.z, abE.w, abO.w);   // A2A2,B2B2
        dst[2] = make_float4(cE.x,  cO.x,  cE.y,  cO.y);    // C1C1,C2C2
    }
    __syncthreads();

    int i = blockIdx.x * 128 + t;
    float2 p = coords[i];
    unsigned long long cxx, cyy;
    PACK2(cxx, p.x, p.x);                 // {cx, cx}
    PACK2(cyy, p.y, p.y);                 // {cy, cy}

    float sum0 = 0.0f, sum1 = 0.0f;       // even / odd gaussian accumulators
    #pragma unroll 8
    for (int gp = 0; gp < N_PAIR; gp++) {
        ulonglong2 q0 = sP[3 * gp + 0];   // {A1pair, B1pair}
        ulonglong2 q1 = sP[3 * gp + 1];   // {A2pair, B2pair}
        ulonglong2 q2 = sP[3 * gp + 2];   // {C1pair, C2pair}
        unsigned long long u, v, ss, t1;
        FMA2(t1, q0.y, cyy, q2.x);        // B1*cy + C1
        FMA2(u,  q0.x, cxx, t1);          // A1*cx + ...
        FMA2(t1, q1.y, cyy, q2.y);        // B2*cy + C2
        FMA2(v,  q1.x, cxx, t1);          // A2*cx + ...
        MUL2(t1, v, v);
        FMA2(ss, u, u, t1);               // {uu+vv even, uu+vv odd}

        float s0, s1;
        UNPACK2(s0, s1, ss);
        float zp0, zp1, th0, th1;
        asm("sqrt.approx.f32 %0, %1;" : "=f"(zp0) : "f"(s0));
        asm("sqrt.approx.f32 %0, %1;" : "=f"(zp1) : "f"(s1));
        asm("tanh.approx.f32 %0, %1;" : "=f"(th0) : "f"(zp0 - 5.0f));
        asm("tanh.approx.f32 %0, %1;" : "=f"(th1) : "f"(zp1 - 5.0f));
        sum0 += th0;
        sum1 += th1;
    }

    // ks = 128 - 0.5*sum + 1e-8 ; H = (1-1e-9)*sigmoid(-10(ks-0.5)) + 1e-9
    float ks = fmaf(-0.5f, sum0 + sum1, 128.0f) + 1e-8f;
    float e = __expf(10.0f * (ks - 0.5f));
    out[i] = (1.0f - 1e-9f) / (1.0f + e) + 1e-9f;
}

extern "C" void kernel_launch(void* const* d_in, const int* in_sizes, int n_in,
                              void* d_out, int out_size) {
    const float4* coords4     = (const float4*)d_in[0];   // 65536 float4 = 131072 pts
    const float2* coords2     = (const float2*)d_in[0];
    const float*  W_scale     = (const float*)d_in[1];
    const float*  W_shape_var = (const float*)d_in[2];
    const float*  W_rotation  = (const float*)d_in[3];
    const float2* W_offsets   = (const float2*)d_in[4];
    float* out = (float*)d_out;

    gs_pre_kernel<<<PRE_BLOCKS, 256>>>(coords4, W_scale, W_shape_var,
                                       W_rotation, W_offsets);
    gs_main_kernel<<<N_POINTS / 128, 128>>>(coords2, out);
}